// round 6
// baseline (speedup 1.0000x reference)
#include <cuda_runtime.h>
#include <cuda_bf16.h>
#include <stdint.h>

#define D_MODEL 4096
#define SHARDS  8
#define N_VOCAB 50400

// Allocation-free scratch.
__device__ float g_bias_sum[D_MODEL];
__device__ int   g_tok_is64;   // 1 if token buffer is int64, 0 if int32

// Prologue: reduce bias over shards AND detect token dtype.
__global__ void prologue_kernel(const float* __restrict__ b,
                                const int* __restrict__ tok32,
                                int tok_words) {
    int d = blockIdx.x * blockDim.x + threadIdx.x;
    if (d < D_MODEL) {
        float s = 0.f;
#pragma unroll
        for (int k = 0; k < SHARDS; k++) s += b[k * D_MODEL + d];
        g_bias_sum[d] = s;
    }
    if (blockIdx.x == 0 && threadIdx.x == 0) {
        // int64 tokens (ids < 50400 << 2^31): every odd 32-bit word is 0.
        // int32 tokens: odd words are random ids; all-zero prob ~ (1/50400)^4.
        int odd_or = 0;
        for (int i = 1; i < 8 && i < tok_words; i += 2) odd_or |= tok32[i];
        g_tok_is64 = (odd_or == 0) ? 1 : 0;
    }
}

// One CTA per token row. 256 threads x 4 float4 = 4096 floats per row.
__global__ __launch_bounds__(256) void embed_gather_kernel(
    const void* __restrict__ tok,        // [T] int32 or int64 ids
    const float* __restrict__ W,         // [N_VOCAB, D_MODEL]
    float* __restrict__ out,             // [T, D_MODEL]
    int T)
{
    const int t = blockIdx.x;
    if (t >= T) return;

    long long id;
    if (g_tok_is64) {
        id = ((const long long*)tok)[t];
    } else {
        id = (long long)((const int*)tok)[t];
    }
    // Clamp defensively: an OOB id would hard-fault; clamped-but-wrong data
    // fails rel_err instead, which is diagnosable.
    if (id < 0) id = 0;
    if (id >= N_VOCAB) id = N_VOCAB - 1;

    const float4* __restrict__ wrow = reinterpret_cast<const float4*>(W + (size_t)id * D_MODEL);
    const float4* __restrict__ bias = reinterpret_cast<const float4*>(g_bias_sum);
    float4* __restrict__ orow = reinterpret_cast<float4*>(out + (size_t)t * D_MODEL);

    const int tid = threadIdx.x;
#pragma unroll
    for (int i = 0; i < 4; i++) {
        int idx = tid + i * 256;                 // 0..1023 float4s
        float4 w = wrow[idx];
        float4 bv = bias[idx];
        w.x += bv.x; w.y += bv.y; w.z += bv.z; w.w += bv.w;
        orow[idx] = w;
    }
}

extern "C" void kernel_launch(void* const* d_in, const int* in_sizes, int n_in,
                              void* d_out, int out_size) {
    // Identify inputs by element count, independent of metadata order.
    const void* tok = nullptr;
    const float* W = nullptr;
    const float* b = nullptr;
    int tok_elems = 0;
    for (int i = 0; i < n_in; i++) {
        long long sz = in_sizes[i];
        if (sz > 100000000LL) {
            W = (const float*)d_in[i];                  // 50400*4096
        } else if (sz == SHARDS * D_MODEL) {
            b = (const float*)d_in[i];                  // 32768
        } else {
            tok = d_in[i];                              // token ids
            tok_elems = (int)sz;
        }
    }

    float* out = (float*)d_out;               // [T, D_MODEL]
    const int T = out_size / D_MODEL;         // 4096

    // tok_words: if int64, buffer has 2*tok_elems 32-bit words; probing the
    // first min(8, 2*elems) words is safe either way.
    prologue_kernel<<<(D_MODEL + 255) / 256, 256>>>(b, (const int*)tok, 2 * tok_elems);
    embed_gather_kernel<<<T, 256>>>(tok, W, out, T);
}

// round 7
// speedup vs baseline: 1.0960x; 1.0960x over previous
#include <cuda_runtime.h>
#include <cuda_bf16.h>
#include <stdint.h>

#define D_MODEL 4096
#define SHARDS  8
#define N_VOCAB 50400

// Allocation-free scratch.
__device__ float g_bias_sum[D_MODEL];
__device__ int   g_tok_is64;   // 1 if token buffer is int64, 0 if int32

// Prologue: reduce bias over shards AND detect token dtype.
// PDL primary: completion (implicit trigger at kernel end) releases the gather.
__global__ void prologue_kernel(const float* __restrict__ b,
                                const int* __restrict__ tok32,
                                int tok_words) {
    int d = blockIdx.x * blockDim.x + threadIdx.x;
    if (d < D_MODEL) {
        float s = 0.f;
#pragma unroll
        for (int k = 0; k < SHARDS; k++) s += b[k * D_MODEL + d];
        g_bias_sum[d] = s;
    }
    if (blockIdx.x == 0 && threadIdx.x == 0) {
        // int64 tokens (ids < 50400 << 2^31): every odd 32-bit word is 0.
        // int32 tokens: odd words are random ids; all-zero prob ~ (1/50400)^4.
        int odd_or = 0;
        for (int i = 1; i < 8 && i < tok_words; i += 2) odd_or |= tok32[i];
        g_tok_is64 = (odd_or == 0) ? 1 : 0;
    }
}

// PDL secondary. 2 token rows per CTA; 256 threads x 4 float4 per row.
// W loads are issued BEFORE the grid-dependency sync (they don't depend on the
// prologue); only the bias read waits.
__global__ __launch_bounds__(256) void embed_gather_kernel(
    const void* __restrict__ tok,        // [T] int32 or int64 ids
    const float* __restrict__ W,         // [N_VOCAB, D_MODEL]
    float* __restrict__ out,             // [T, D_MODEL]
    int T)
{
    const int t0 = 2 * blockIdx.x;
    const int t1 = t0 + 1;
    const int tid = threadIdx.x;

    // Token ids: the tok buffer is input data, independent of the prologue.
    // Dtype flag g_tok_is64 IS written by the prologue, so read ids both ways
    // and select after the sync? No: keep it simple — the flag is the only
    // prologue-dependent scalar needed early. Read raw words now, decide later.
    const int*       t32 = (const int*)tok;
    const long long* t64 = (const long long*)tok;
    // Load both interpretations (cheap: 2-3 scalar loads from L2).
    long long id0_64 = t64[t0];
    long long id1_64 = (t1 < T) ? t64[t1] : 0;
    int       id0_32 = t32[t0];
    int       id1_32 = (t1 < T) ? t32[t1] : 0;

    // Must know dtype before indexing W -> sync on the prologue now.
    // CTAs are already resident (PDL), so this costs ~0 once prologue ends.
    cudaGridDependencySynchronize();

    long long id0 = g_tok_is64 ? id0_64 : (long long)id0_32;
    long long id1 = g_tok_is64 ? id1_64 : (long long)id1_32;
    if (id0 < 0) id0 = 0; if (id0 >= N_VOCAB) id0 = N_VOCAB - 1;
    if (id1 < 0) id1 = 0; if (id1 >= N_VOCAB) id1 = N_VOCAB - 1;

    const float4* __restrict__ w0   = reinterpret_cast<const float4*>(W + (size_t)id0 * D_MODEL);
    const float4* __restrict__ w1   = reinterpret_cast<const float4*>(W + (size_t)id1 * D_MODEL);
    const float4* __restrict__ bias = reinterpret_cast<const float4*>(g_bias_sum);
    float4* __restrict__ o0 = reinterpret_cast<float4*>(out + (size_t)t0 * D_MODEL);
    float4* __restrict__ o1 = reinterpret_cast<float4*>(out + (size_t)t1 * D_MODEL);

    // Issue all 12 loads up front for max MLP, then add+store.
    float4 a[4], c[4], bv[4];
#pragma unroll
    for (int i = 0; i < 4; i++) a[i]  = __ldcs(&w0[tid + i * 256]);
#pragma unroll
    for (int i = 0; i < 4; i++) c[i]  = __ldcs(&w1[tid + i * 256]);
#pragma unroll
    for (int i = 0; i < 4; i++) bv[i] = __ldg(&bias[tid + i * 256]);

#pragma unroll
    for (int i = 0; i < 4; i++) {
        float4 r0 = a[i], r1 = c[i], bb = bv[i];
        r0.x += bb.x; r0.y += bb.y; r0.z += bb.z; r0.w += bb.w;
        r1.x += bb.x; r1.y += bb.y; r1.z += bb.z; r1.w += bb.w;
        __stcs(&o0[tid + i * 256], r0);
        if (t1 < T) __stcs(&o1[tid + i * 256], r1);
    }
}

extern "C" void kernel_launch(void* const* d_in, const int* in_sizes, int n_in,
                              void* d_out, int out_size) {
    // Identify inputs by element count, independent of metadata order.
    const void* tok = nullptr;
    const float* W = nullptr;
    const float* b = nullptr;
    int tok_elems = 0;
    for (int i = 0; i < n_in; i++) {
        long long sz = in_sizes[i];
        if (sz > 100000000LL) {
            W = (const float*)d_in[i];                  // 50400*4096
        } else if (sz == SHARDS * D_MODEL) {
            b = (const float*)d_in[i];                  // 32768
        } else {
            tok = d_in[i];                              // token ids
            tok_elems = (int)sz;
        }
    }

    float* out = (float*)d_out;               // [T, D_MODEL]
    const int T = out_size / D_MODEL;         // 4096

    // Primary (normal launch on legacy default stream, as captured by harness).
    prologue_kernel<<<(D_MODEL + 255) / 256, 256>>>(b, (const int*)tok, 2 * tok_elems);

    // Secondary with programmatic stream serialization: its CTAs launch while
    // the prologue is still running; cudaGridDependencySynchronize() inside
    // gates only the prologue-dependent reads.
    cudaLaunchConfig_t cfg = {};
    cfg.gridDim  = dim3((unsigned)((T + 1) / 2));
    cfg.blockDim = dim3(256);
    cfg.dynamicSmemBytes = 0;
    cfg.stream = 0;  // legacy default stream (same as <<<>>>)
    cudaLaunchAttribute attr[1];
    attr[0].id = cudaLaunchAttributeProgrammaticStreamSerialization;
    attr[0].val.programmaticStreamSerializationAllowed = 1;
    cfg.attrs = attr;
    cfg.numAttrs = 1;
    cudaLaunchKernelEx(&cfg, embed_gather_kernel, tok, W, out, T);
}

// round 10
// speedup vs baseline: 1.1752x; 1.0723x over previous
#include <cuda_runtime.h>
#include <cuda_bf16.h>
#include <stdint.h>

#define D_MODEL 4096
#define SHARDS  8
#define N_VOCAB 50400

// Allocation-free scratch.
__device__ float g_bias_sum[D_MODEL];

// Prologue (PDL primary): reduce bias over shards only.
__global__ void prologue_kernel(const float* __restrict__ b) {
    int d = blockIdx.x * blockDim.x + threadIdx.x;
    if (d < D_MODEL) {
        float s = 0.f;
#pragma unroll
        for (int k = 0; k < SHARDS; k++) s += b[k * D_MODEL + d];
        g_bias_sum[d] = s;
    }
}

// PDL secondary. 2 token rows per CTA; 256 threads x 4 float4 per row.
// Token dtype is detected LOCALLY (two int4 loads), so all W loads are issued
// with no dependence on the prologue; only the bias read sits behind the
// grid-dependency sync.
__global__ __launch_bounds__(256) void embed_gather_kernel(
    const void* __restrict__ tok,        // [T] int32 or int64 ids
    const float* __restrict__ W,         // [N_VOCAB, D_MODEL]
    float* __restrict__ out,             // [T, D_MODEL]
    int T)
{
    const int t0 = 2 * blockIdx.x;
    const int t1 = t0 + 1;
    const int tid = threadIdx.x;

    // Local dtype detection: for int64 ids (< 50400 << 2^31) every odd 32-bit
    // word of the buffer is 0; for int32 ids the odd words are random tokens
    // (all-zero probability ~ (1/50400)^4). Same data -> same answer in every
    // CTA. Two 16B loads, L2-resident after the first CTA touches them.
    const int4* tq = (const int4*)tok;
    int4 q0 = tq[0], q1 = tq[1];
    const bool is64 = ((q0.y | q0.w | q1.y | q1.w) == 0);

    const int*       t32 = (const int*)tok;
    const long long* t64 = (const long long*)tok;
    long long id0 = is64 ? t64[t0] : (long long)t32[t0];
    long long id1 = (t1 < T) ? (is64 ? t64[t1] : (long long)t32[t1]) : 0;

    // Clamp defensively: OOB would hard-fault; wrong-but-inbounds fails
    // rel_err instead, which is diagnosable.
    if (id0 < 0) id0 = 0; if (id0 >= N_VOCAB) id0 = N_VOCAB - 1;
    if (id1 < 0) id1 = 0; if (id1 >= N_VOCAB) id1 = N_VOCAB - 1;

    const float4* __restrict__ w0 = reinterpret_cast<const float4*>(W + (size_t)id0 * D_MODEL);
    const float4* __restrict__ w1 = reinterpret_cast<const float4*>(W + (size_t)id1 * D_MODEL);

    // Issue all 8 W loads up front — independent of the prologue.
    float4 a[4], c[4];
#pragma unroll
    for (int i = 0; i < 4; i++) a[i] = __ldcs(&w0[tid + i * 256]);
#pragma unroll
    for (int i = 0; i < 4; i++) c[i] = __ldcs(&w1[tid + i * 256]);

    // Now gate only the prologue-dependent bias read. The prologue (16 CTAs)
    // completes well inside the W-load shadow, so this wait is ~free.
    cudaGridDependencySynchronize();

    const float4* __restrict__ bias = reinterpret_cast<const float4*>(g_bias_sum);
    float4 bv[4];
#pragma unroll
    for (int i = 0; i < 4; i++) bv[i] = __ldg(&bias[tid + i * 256]);

    float4* __restrict__ o0 = reinterpret_cast<float4*>(out + (size_t)t0 * D_MODEL);
    float4* __restrict__ o1 = reinterpret_cast<float4*>(out + (size_t)t1 * D_MODEL);

#pragma unroll
    for (int i = 0; i < 4; i++) {
        float4 r0 = a[i], r1 = c[i], bb = bv[i];
        r0.x += bb.x; r0.y += bb.y; r0.z += bb.z; r0.w += bb.w;
        r1.x += bb.x; r1.y += bb.y; r1.z += bb.z; r1.w += bb.w;
        __stcs(&o0[tid + i * 256], r0);
        if (t1 < T) __stcs(&o1[tid + i * 256], r1);
    }
}

extern "C" void kernel_launch(void* const* d_in, const int* in_sizes, int n_in,
                              void* d_out, int out_size) {
    // Identify inputs by element count, independent of metadata order.
    const void* tok = nullptr;
    const float* W = nullptr;
    const float* b = nullptr;
    for (int i = 0; i < n_in; i++) {
        long long sz = in_sizes[i];
        if (sz > 100000000LL)            W   = (const float*)d_in[i];  // 50400*4096
        else if (sz == SHARDS * D_MODEL) b   = (const float*)d_in[i];  // 32768
        else                             tok = d_in[i];                // token ids
    }

    float* out = (float*)d_out;               // [T, D_MODEL]
    const int T = out_size / D_MODEL;         // 4096

    // Primary.
    prologue_kernel<<<(D_MODEL + 255) / 256, 256>>>(b);

    // Secondary with programmatic stream serialization: its CTAs launch and run
    // their W-load phase while the prologue is still in flight.
    cudaLaunchConfig_t cfg = {};
    cfg.gridDim  = dim3((unsigned)((T + 1) / 2));
    cfg.blockDim = dim3(256);
    cfg.dynamicSmemBytes = 0;
    cfg.stream = 0;  // legacy default stream (same as <<<>>>)
    cudaLaunchAttribute attr[1];
    attr[0].id = cudaLaunchAttributeProgrammaticStreamSerialization;
    attr[0].val.programmaticStreamSerializationAllowed = 1;
    cfg.attrs = attr;
    cfg.numAttrs = 1;
    cudaLaunchKernelEx(&cfg, embed_gather_kernel, tok, W, out, T);
}